// round 3
// baseline (speedup 1.0000x reference)
#include <cuda_runtime.h>
#include <math.h>

typedef unsigned long long ull;

#define B_    64
#define NDML  6000
#define DF    512
#define P_    24960
#define DIM   2048
#define KNN   10

// scratch (device globals; no allocation)
__device__ float g_dmlnorm[NDML];
__device__ float g_clspart[32 * B_ * DF];
__device__ float g_cls[B_ * DF];
__device__ float g_scorepart[6 * B_ * NDML];
__device__ int   g_idx[B_ * KNN];
__device__ float g_embed[B_ * P_];
__device__ float g_qpart[37 * B_ * DIM];
__device__ float g_q[B_ * DIM];
__device__ float g_tpart[3 * B_ * P_];
__device__ float g_spart[12 * B_ * 20];
__device__ float g_attn[B_ * 20];

__device__ __forceinline__ ull fma2(ull a, ull b, ull c) {
    ull d; asm("fma.rn.f32x2 %0, %1, %2, %3;" : "=l"(d) : "l"(a), "l"(b), "l"(c)); return d;
}
__device__ __forceinline__ ull pk2(float v) {
    ull r; unsigned u = __float_as_uint(v);
    asm("mov.b64 %0, {%1, %2};" : "=l"(r) : "r"(u), "r"(u)); return r;
}
__device__ __forceinline__ float2 up2(ull v) {
    unsigned lo, hi; asm("mov.b64 {%0, %1}, %2;" : "=r"(lo), "=r"(hi) : "l"(v));
    return make_float2(__uint_as_float(lo), __uint_as_float(hi));
}

// GEMM NN: Cpart[split][64][N] = A[64][K] @ B[K][N]; tile 128n x 64b, k-step 32.
__global__ __launch_bounds__(256) void gemm_nn(const float* __restrict__ A,
                                               const float* __restrict__ Bm,
                                               float* __restrict__ Cpart,
                                               int N, int K, int kchunk)
{
    __shared__ __align__(16) float As[32][64];
    __shared__ __align__(16) float Bs[32][128];
    const int t = threadIdx.x, tn = t & 31, tb = t >> 5;
    const int n0 = blockIdx.x * 128;
    const int k0 = blockIdx.y * kchunk;
    const int kend = min(k0 + kchunk, K);

    ull acc[4][4];
#pragma unroll
    for (int j = 0; j < 4; j++)
#pragma unroll
        for (int i = 0; i < 4; i++) acc[j][i] = 0ull;

    const int lb = t >> 2, lq = t & 3;
    const int lr = t >> 5, lc = t & 31;

    for (int k = k0; k < kend; k += 32) {
        const float* ap = A + (size_t)lb * K + k + lq * 8;
        float4 a0 = *(const float4*)ap;
        float4 a1 = *(const float4*)(ap + 4);
        As[lq*8+0][lb]=a0.x; As[lq*8+1][lb]=a0.y; As[lq*8+2][lb]=a0.z; As[lq*8+3][lb]=a0.w;
        As[lq*8+4][lb]=a1.x; As[lq*8+5][lb]=a1.y; As[lq*8+6][lb]=a1.z; As[lq*8+7][lb]=a1.w;
#pragma unroll
        for (int i = 0; i < 4; i++)
            *(float4*)&Bs[lr + i*8][lc*4] =
                *(const float4*)(Bm + (size_t)(k + lr + i*8) * N + n0 + lc*4);
        __syncthreads();
#pragma unroll 8
        for (int kk = 0; kk < 32; kk++) {
            float4 w = *(const float4*)&Bs[kk][tn*4];
            ull w0 = pk2(w.x), w1 = pk2(w.y), w2 = pk2(w.z), w3 = pk2(w.w);
            const ull* ep = (const ull*)&As[kk][tb*8];
            ull e0 = ep[0], e1 = ep[1], e2 = ep[2], e3 = ep[3];
            acc[0][0]=fma2(e0,w0,acc[0][0]); acc[0][1]=fma2(e0,w1,acc[0][1]);
            acc[0][2]=fma2(e0,w2,acc[0][2]); acc[0][3]=fma2(e0,w3,acc[0][3]);
            acc[1][0]=fma2(e1,w0,acc[1][0]); acc[1][1]=fma2(e1,w1,acc[1][1]);
            acc[1][2]=fma2(e1,w2,acc[1][2]); acc[1][3]=fma2(e1,w3,acc[1][3]);
            acc[2][0]=fma2(e2,w0,acc[2][0]); acc[2][1]=fma2(e2,w1,acc[2][1]);
            acc[2][2]=fma2(e2,w2,acc[2][2]); acc[2][3]=fma2(e2,w3,acc[2][3]);
            acc[3][0]=fma2(e3,w0,acc[3][0]); acc[3][1]=fma2(e3,w1,acc[3][1]);
            acc[3][2]=fma2(e3,w2,acc[3][2]); acc[3][3]=fma2(e3,w3,acc[3][3]);
        }
        __syncthreads();
    }
    float* cp = Cpart + (size_t)blockIdx.y * ((size_t)B_ * N);
#pragma unroll
    for (int j = 0; j < 4; j++) {
        float2 u0 = up2(acc[j][0]), u1 = up2(acc[j][1]), u2 = up2(acc[j][2]), u3 = up2(acc[j][3]);
        int be = tb * 8 + 2 * j;
        *(float4*)&cp[(size_t)be * N + n0 + tn*4]     = make_float4(u0.x, u1.x, u2.x, u3.x);
        *(float4*)&cp[(size_t)(be+1) * N + n0 + tn*4] = make_float4(u0.y, u1.y, u2.y, u3.y);
    }
}

// GEMM NT: Cpart[split][64][P] = A[64][KD] @ Bt[P][KD]^T
__global__ __launch_bounds__(256) void gemm_nt(const float* __restrict__ A,
                                               const float* __restrict__ Bt,
                                               float* __restrict__ Cpart,
                                               int P, int KD, int kchunk)
{
    __shared__ __align__(16) float As[32][64];
    __shared__ __align__(16) float Ws[32][128];
    const int t = threadIdx.x, tn = t & 31, tb = t >> 5;
    const int p0 = blockIdx.x * 128;
    const int k0 = blockIdx.y * kchunk;
    const int kend = min(k0 + kchunk, KD);

    ull acc[4][4];
#pragma unroll
    for (int j = 0; j < 4; j++)
#pragma unroll
        for (int i = 0; i < 4; i++) acc[j][i] = 0ull;

    const int lb = t >> 2, lq = t & 3;
    const int lp = t >> 3, l8 = t & 7;

    for (int k = k0; k < kend; k += 32) {
        const float* ap = A + (size_t)lb * KD + k + lq * 8;
        float4 a0 = *(const float4*)ap;
        float4 a1 = *(const float4*)(ap + 4);
        As[lq*8+0][lb]=a0.x; As[lq*8+1][lb]=a0.y; As[lq*8+2][lb]=a0.z; As[lq*8+3][lb]=a0.w;
        As[lq*8+4][lb]=a1.x; As[lq*8+5][lb]=a1.y; As[lq*8+6][lb]=a1.z; As[lq*8+7][lb]=a1.w;
#pragma unroll
        for (int i = 0; i < 4; i++) {
            int pr = lp + i * 32;
            int pg = p0 + pr;
            float4 wv = make_float4(0.f, 0.f, 0.f, 0.f);
            if (pg < P) wv = *(const float4*)(Bt + (size_t)pg * KD + k + l8 * 4);
            Ws[l8*4+0][pr] = wv.x; Ws[l8*4+1][pr] = wv.y;
            Ws[l8*4+2][pr] = wv.z; Ws[l8*4+3][pr] = wv.w;
        }
        __syncthreads();
#pragma unroll 8
        for (int kk = 0; kk < 32; kk++) {
            float4 w = *(const float4*)&Ws[kk][tn*4];
            ull w0 = pk2(w.x), w1 = pk2(w.y), w2 = pk2(w.z), w3 = pk2(w.w);
            const ull* ep = (const ull*)&As[kk][tb*8];
            ull e0 = ep[0], e1 = ep[1], e2 = ep[2], e3 = ep[3];
            acc[0][0]=fma2(e0,w0,acc[0][0]); acc[0][1]=fma2(e0,w1,acc[0][1]);
            acc[0][2]=fma2(e0,w2,acc[0][2]); acc[0][3]=fma2(e0,w3,acc[0][3]);
            acc[1][0]=fma2(e1,w0,acc[1][0]); acc[1][1]=fma2(e1,w1,acc[1][1]);
            acc[1][2]=fma2(e1,w2,acc[1][2]); acc[1][3]=fma2(e1,w3,acc[1][3]);
            acc[2][0]=fma2(e2,w0,acc[2][0]); acc[2][1]=fma2(e2,w1,acc[2][1]);
            acc[2][2]=fma2(e2,w2,acc[2][2]); acc[2][3]=fma2(e2,w3,acc[2][3]);
            acc[3][0]=fma2(e3,w0,acc[3][0]); acc[3][1]=fma2(e3,w1,acc[3][1]);
            acc[3][2]=fma2(e3,w2,acc[3][2]); acc[3][3]=fma2(e3,w3,acc[3][3]);
        }
        __syncthreads();
    }
    float* cp = Cpart + (size_t)blockIdx.y * ((size_t)B_ * P);
    int p = p0 + tn * 4;
    if (p < P) {
#pragma unroll
        for (int j = 0; j < 4; j++) {
            float2 u0 = up2(acc[j][0]), u1 = up2(acc[j][1]), u2 = up2(acc[j][2]), u3 = up2(acc[j][3]);
            int be = tb * 8 + 2 * j;
            *(float4*)&cp[(size_t)be * P + p]     = make_float4(u0.x, u1.x, u2.x, u3.x);
            *(float4*)&cp[(size_t)(be+1) * P + p] = make_float4(u0.y, u1.y, u2.y, u3.y);
        }
    }
}

// deterministic split-K reduce
__global__ void reduce_k(const float* __restrict__ part, float* __restrict__ out, int S, int len4)
{
    int i = blockIdx.x * blockDim.x + threadIdx.x;
    if (i >= len4) return;
    const float4* p4 = (const float4*)part;
    float4 s = p4[i];
    for (int ss = 1; ss < S; ss++) {
        float4 v = p4[(size_t)ss * len4 + i];
        s.x += v.x; s.y += v.y; s.z += v.z; s.w += v.w;
    }
    ((float4*)out)[i] = s;
}

__global__ void dmlnorm_k(const float* __restrict__ dml, float* __restrict__ dn)
{
    int w = threadIdx.x >> 5, lane = threadIdx.x & 31;
    int r = blockIdx.x * 8 + w;
    const float4* row = (const float4*)(dml + (size_t)r * DF);
    float s = 0.f;
#pragma unroll
    for (int i = 0; i < 4; i++) {
        float4 v = row[lane + i * 32];
        s += v.x*v.x + v.y*v.y + v.z*v.z + v.w*v.w;
    }
    for (int off = 16; off; off >>= 1) s += __shfl_down_sync(0xffffffffu, s, off);
    if (lane == 0) dn[r] = s;
}

// top-10 smallest of key = ||dml||^2 - 2*cls.dml (sqrt & ||cls||^2 dropped: rank-equal)
__global__ void topk_k(const float* __restrict__ spart, const float* __restrict__ dnorm,
                       int* __restrict__ idxo)
{
    int b = blockIdx.x, t = threadIdx.x;
    __shared__ float sv[NDML];
    __shared__ ull red[256];
    for (int j = t; j < NDML; j += 256) {
        float dot = 0.f;
#pragma unroll
        for (int s = 0; s < 6; s++) dot += spart[(size_t)s * (B_ * NDML) + b * NDML + j];
        sv[j] = dnorm[j] - 2.f * dot;
    }
    __syncthreads();
    for (int r = 0; r < KNN; r++) {
        ull best = ~0ull;
        for (int j = t; j < NDML; j += 256) {
            unsigned u = __float_as_uint(sv[j]);
            u = (u & 0x80000000u) ? ~u : (u | 0x80000000u);
            ull key = ((ull)u << 32) | (unsigned)j;
            if (key < best) best = key;
        }
        red[t] = best;
        __syncthreads();
        for (int off = 128; off; off >>= 1) {
            if (t < off) { if (red[t + off] < red[t]) red[t] = red[t + off]; }
            __syncthreads();
        }
        int jw = (int)(red[0] & 0xffffffffu);
        if (t == 0) { idxo[b * KNN + r] = jw; sv[jw] = 3.4e38f; }
        __syncthreads();
    }
}

// patch embedding -> embed[64][24960]
__global__ void embed_k(const float* __restrict__ x, const float* __restrict__ Wp,
                        const float* __restrict__ clst, float* __restrict__ E)
{
    int tok = blockIdx.x, b = blockIdx.y, h = threadIdx.x;
    if (tok == 0) { E[(size_t)b * P_ + h] = clst[h]; return; }
    __shared__ float pn[48];
    int pt = tok - 1, gr = pt >> 3, gc = pt & 7;
    if (h < 48) {
        int c = h >> 4, rem = h & 15, pr = rem >> 2, pc = rem & 3;
        float mean = (c == 0) ? 0.4914f : ((c == 1) ? 0.4822f : 0.4465f);
        float inv  = (c == 0) ? 4.048582995951417f : ((c == 1) ? 4.106776180698152f : 3.822629969418960f);
        float v = x[(((size_t)b * 3 + c) * 32 + gr * 4 + pr) * 32 + gc * 4 + pc];
        pn[h] = (v - mean) * inv;
    }
    __syncthreads();
    float acc = 0.f;
#pragma unroll
    for (int f = 0; f < 48; f++) acc += pn[f] * Wp[f * 384 + h];
    E[(size_t)b * P_ + tok * 384 + h] = acc;
}

// gather-dot scores over 2080-wide chunks; sums the 3 t-splits inline
__global__ __launch_bounds__(256) void scores_k(const float* __restrict__ tpart,
                                                const float* __restrict__ OTin,
                                                const float* __restrict__ OTout,
                                                const int* __restrict__ idx,
                                                float* __restrict__ spart)
{
    int c = blockIdx.x, b = blockIdx.y, t = threadIdx.x;
    __shared__ __align__(16) float ts[2080];
    __shared__ int ids[10];
    __shared__ float warr[8];
    int base4 = (b * P_ + c * 2080) >> 2;
    const float4* t0 = (const float4*)tpart + base4;
    const float4* t1 = t0 + ((B_ * P_) >> 2);
    const float4* t2 = t1 + ((B_ * P_) >> 2);
    for (int i = t; i < 520; i += 256) {
        float4 a = t0[i], bb = t1[i], cc = t2[i];
        ((float4*)ts)[i] = make_float4(a.x + bb.x + cc.x, a.y + bb.y + cc.y,
                                       a.z + bb.z + cc.z, a.w + bb.w + cc.w);
    }
    if (t < 10) ids[t] = idx[b * 10 + t];
    __syncthreads();

    float pacc[20];
#pragma unroll
    for (int n = 0; n < 20; n++) pacc[n] = 0.f;
#pragma unroll 1
    for (int n = 0; n < 20; n++) {
        const float* row = ((n < 10) ? OTin : OTout) + (size_t)ids[n % 10] * P_ + c * 2080;
        const float4* r4 = (const float4*)row;
        float s = 0.f;
        for (int i = t; i < 520; i += 256) {
            float4 v = r4[i]; float4 tt = ((float4*)ts)[i];
            s += v.x * tt.x + v.y * tt.y + v.z * tt.z + v.w * tt.w;
        }
        pacc[n] = s;
    }
    int lane = t & 31, wid = t >> 5;
    for (int n = 0; n < 20; n++) {
        float v = pacc[n];
        for (int off = 16; off; off >>= 1) v += __shfl_down_sync(0xffffffffu, v, off);
        if (lane == 0) warr[wid] = v;
        __syncthreads();
        if (t == 0) {
            float s = 0.f;
            for (int w = 0; w < 8; w++) s += warr[w];
            spart[((size_t)c * B_ + b) * 20 + n] = s;
        }
        __syncthreads();
    }
}

__global__ void softmax_k(const float* __restrict__ spart, float* __restrict__ attn)
{
    int b = blockIdx.x, n = threadIdx.x;
    float s = -3.4e38f;
    if (n < 20) {
        float acc = 0.f;
        for (int c = 0; c < 12; c++) acc += spart[((size_t)c * B_ + b) * 20 + n];
        s = acc * 0.022097086912079608f;
    }
    float m = s;
    for (int off = 16; off; off >>= 1) m = fmaxf(m, __shfl_xor_sync(0xffffffffu, m, off));
    float e = (n < 20) ? expf(s - m) : 0.f;
    float sum = e;
    for (int off = 16; off; off >>= 1) sum += __shfl_xor_sync(0xffffffffu, sum, off);
    if (n < 20) attn[b * 20 + n] = e / sum;
}

__global__ __launch_bounds__(256) void out_k(const float* __restrict__ OTin,
                                             const float* __restrict__ OTout,
                                             const int* __restrict__ idx,
                                             const float* __restrict__ attn,
                                             float* __restrict__ out)
{
    int c = blockIdx.x, b = blockIdx.y, t = threadIdx.x;
    __shared__ float a[20];
    __shared__ int ids[10];
    if (t < 20) a[t] = attn[b * 20 + t];
    if (t < 10) ids[t] = idx[b * 10 + t];
    __syncthreads();
    const float4* rows[20];
#pragma unroll
    for (int n = 0; n < 20; n++)
        rows[n] = (const float4*)(((n < 10) ? OTin : OTout) + (size_t)ids[n % 10] * P_ + c * 2080);
    float4* o4 = (float4*)(out + (size_t)b * P_ + c * 2080);
    for (int i = t; i < 520; i += 256) {
        float4 s = make_float4(0.f, 0.f, 0.f, 0.f);
#pragma unroll
        for (int n = 0; n < 20; n++) {
            float4 v = rows[n][i]; float an = a[n];
            s.x += an * v.x; s.y += an * v.y; s.z += an * v.z; s.w += an * v.w;
        }
        o4[i] = s;
    }
}

extern "C" void kernel_launch(void* const* d_in, const int* in_sizes, int n_in,
                              void* d_out, int out_size)
{
    const float* x     = (const float*)d_in[0];
    const float* dml   = (const float*)d_in[1];
    const float* OTin  = (const float*)d_in[2];
    const float* OTout = (const float*)d_in[3];
    const float* Wdml  = (const float*)d_in[4];
    const float* Wp    = (const float*)d_in[5];
    const float* clst  = (const float*)d_in[6];
    const float* Wq    = (const float*)d_in[7];
    const float* Wk    = (const float*)d_in[8];
    float* out = (float*)d_out;

    float *clspart, *cls, *dnorm, *scorepart, *embed, *qpart, *q, *tpart, *spart, *attn;
    int* idx;
    cudaGetSymbolAddress((void**)&clspart,  g_clspart);
    cudaGetSymbolAddress((void**)&cls,      g_cls);
    cudaGetSymbolAddress((void**)&dnorm,    g_dmlnorm);
    cudaGetSymbolAddress((void**)&scorepart,g_scorepart);
    cudaGetSymbolAddress((void**)&idx,      g_idx);
    cudaGetSymbolAddress((void**)&embed,    g_embed);
    cudaGetSymbolAddress((void**)&qpart,    g_qpart);
    cudaGetSymbolAddress((void**)&q,        g_q);
    cudaGetSymbolAddress((void**)&tpart,    g_tpart);
    cudaGetSymbolAddress((void**)&spart,    g_spart);
    cudaGetSymbolAddress((void**)&attn,     g_attn);

    // 1. cls = x_flat @ W_dml   [64,3072]@[3072,512], split-K 32x96
    gemm_nn<<<dim3(4, 32), 256>>>(x, Wdml, clspart, DF, 3072, 96);
    reduce_k<<<32, 256>>>(clspart, cls, 32, (B_ * DF) / 4);
    // 2. dml row norms
    dmlnorm_k<<<750, 256>>>(dml, dnorm);
    // 3. scores = cls @ dml^T   [64,512]@[6000,512]^T, split-K 6x96
    gemm_nt<<<dim3(47, 6), 256>>>(cls, dml, scorepart, NDML, DF, 96);
    // 4. top-10
    topk_k<<<64, 256>>>(scorepart, dnorm, idx);
    // 5. patch embedding
    embed_k<<<dim3(65, 64), 384>>>(x, Wp, clst, embed);
    // 6. q = embed @ Wq   [64,24960]@[24960,2048], split-K 37x704
    gemm_nn<<<dim3(16, 37), 256>>>(embed, Wq, qpart, DIM, P_, 704);
    reduce_k<<<128, 256>>>(qpart, q, 37, (B_ * DIM) / 4);
    // 7. t = q @ Wk^T   [64,2048]@[24960,2048]^T, split-K 3x704
    gemm_nt<<<dim3(195, 3), 256>>>(q, Wk, tpart, P_, DIM, 704);
    // 8. gathered dot scores
    scores_k<<<dim3(12, 64), 256>>>(tpart, OTin, OTout, idx, spart);
    // 9. softmax over 20 neighbors
    softmax_k<<<64, 32>>>(spart, attn);
    // 10. weighted neighbor sum -> output
    out_k<<<dim3(12, 64), 256>>>(OTin, OTout, idx, attn, out);
}